// round 16
// baseline (speedup 1.0000x reference)
#include <cuda_runtime.h>
#include <cuda_fp16.h>
#include <mma.h>
#include <math.h>

using namespace nvcuda;

#define N_USER   100000
#define N_ITEM   50000
#define N_NODES_ (N_USER + N_ITEM)   // 150000
#define NNZ_     4800000
#define EMB      64
#define N_LAYERS 3
#define BATCH_   16384
#define EPS_     1e-12f
#define NEG_SLOPE 0.2f

// shared-memory layout constants for transform (bytes)
#define A_LD   136                    // halves per row of A=[S|P], 272B
#define B_LD   72                     // halves per row of B=[Wg;Wb]
#define C_LD   72                     // floats per row of C
#define SH_A   0
#define SH_B   (64 * A_LD * 2)                    // 17408
#define SH_C   (SH_B + 128 * B_LD * 2)            // 35840
#define SH_BS  (SH_C + 64 * C_LD * 4)             // 54272
#define SH_TOT (SH_BS + 64 * 4)                   // 54528

// ---------------- scratch (device globals: allocation-free rule) -------------
__device__ __half g_ego_h [N_NODES_ * EMB];     // fp16 ego
__device__ __half g_side_h[N_NODES_ * EMB];     // fp16 A_hat @ ego
__device__ __half g_all_h [N_NODES_ * 4 * EMB]; // fp16 concat of 4 blocks (76.8MB)
// CSR build scratch.  g_row_cnt is zero-initialized at module load and
// re-zeroed by scan_kernel after it is consumed -> every replay sees zeros.
__device__ int   g_row_cnt[N_NODES_];
__device__ int   g_row_cur[N_NODES_];           // seeded with row offsets by scan
__device__ int   g_row_off[N_NODES_ + 1];
__device__ int2  g_edge_s [NNZ_];               // packed (col, val_bits), row-sorted

// ------- init: ego_h = fp16(concat(ue, ie)); g_all[:,0:64] = fp16; count -----
__global__ void init_kernel(const float* __restrict__ ue, const float* __restrict__ ie,
                            const int* __restrict__ rows) {
    int idx = blockIdx.x * blockDim.x + threadIdx.x;      // half4 (uint2) index
    const int total = N_NODES_ * EMB / 4;                 // 2.4M
    if (idx < total) {
        int node = idx >> 4;
        int c4   = idx & 15;
        float4 v;
        if (node < N_USER) v = __ldg((const float4*)ue + node * 16 + c4);
        else               v = __ldg((const float4*)ie + (node - N_USER) * 16 + c4);
        __half2 h0 = __floats2half2_rn(v.x, v.y);
        __half2 h1 = __floats2half2_rn(v.z, v.w);
        uint2 pk;
        pk.x = *(unsigned*)&h0;
        pk.y = *(unsigned*)&h1;
        ((uint2*)g_ego_h)[idx] = pk;
        ((uint2*)g_all_h)[node * 64 + c4] = pk;   // row = 256 halves = 64 uint2
    }
    if (idx < NNZ_ / 4) {             // fused degree count (cnt pre-zeroed)
        int4 r4 = __ldg((const int4*)rows + idx);
        atomicAdd(&g_row_cnt[r4.x], 1);
        atomicAdd(&g_row_cnt[r4.y], 1);
        atomicAdd(&g_row_cnt[r4.z], 1);
        atomicAdd(&g_row_cnt[r4.w], 1);
    }
}

// ---------------- CSR build: coalesced wave-scan (single block, 1024 thr) ----
__global__ void scan_kernel() {
    __shared__ int warp_sums[32];
    const int NWAVES = (N_NODES_ + 1023) / 1024;   // 147
    int t    = threadIdx.x;
    int lane = t & 31;
    int wid  = t >> 5;
    int carry = 0;
    for (int w = 0; w < NWAVES; w++) {
        int idx = w * 1024 + t;
        int c = 0;
        if (idx < N_NODES_) {
            c = g_row_cnt[idx];
            g_row_cnt[idx] = 0;     // reset for next replay
        }
        int x = c;                  // inclusive warp scan
#pragma unroll
        for (int off = 1; off < 32; off <<= 1) {
            int y = __shfl_up_sync(0xffffffffu, x, off);
            if (lane >= off) x += y;
        }
        if (lane == 31) warp_sums[wid] = x;
        __syncthreads();
        if (wid == 0) {
            int wv = warp_sums[lane];
#pragma unroll
            for (int off = 1; off < 32; off <<= 1) {
                int y = __shfl_up_sync(0xffffffffu, wv, off);
                if (lane >= off) wv += y;
            }
            warp_sums[lane] = wv;
        }
        __syncthreads();
        int warp_excl = (wid > 0) ? warp_sums[wid - 1] : 0;
        int excl = carry + warp_excl + (x - c);
        if (idx < N_NODES_) {
            g_row_off[idx] = excl;
            g_row_cur[idx] = excl;  // cursor starts at row start
        }
        carry += warp_sums[31];
        __syncthreads();
    }
    if (t == 0) g_row_off[N_NODES_] = carry;   // total = NNZ
}

// ---------------- CSR build: scatter edges (16 chains/thread, MLP=16) --------
__global__ void scatter_kernel(const int* __restrict__ rows,
                               const int* __restrict__ cols,
                               const int* __restrict__ vals) {
    int q = blockIdx.x * blockDim.x + threadIdx.x;   // 16-edge group id
    if (q >= NNZ_ / 16) return;
    int r[16], c[16], v[16], p[16];
#pragma unroll
    for (int g = 0; g < 4; g++) {
        int4 rr = __ldg((const int4*)rows + q * 4 + g);
        int4 cc = __ldg((const int4*)cols + q * 4 + g);
        int4 vv = __ldg((const int4*)vals + q * 4 + g);
        r[g * 4 + 0] = rr.x; r[g * 4 + 1] = rr.y; r[g * 4 + 2] = rr.z; r[g * 4 + 3] = rr.w;
        c[g * 4 + 0] = cc.x; c[g * 4 + 1] = cc.y; c[g * 4 + 2] = cc.z; c[g * 4 + 3] = cc.w;
        v[g * 4 + 0] = vv.x; v[g * 4 + 1] = vv.y; v[g * 4 + 2] = vv.z; v[g * 4 + 3] = vv.w;
    }
#pragma unroll
    for (int u = 0; u < 16; u++) p[u] = atomicAdd(&g_row_cur[r[u]], 1);
#pragma unroll
    for (int u = 0; u < 16; u++) g_edge_s[p[u]] = make_int2(c[u], v[u]);
}

// ---------------- CSR SpMM: fp16 gather (16B/lane), fp32 accum, fp16 store ----
// 8 lanes per row; each lane owns 8 consecutive columns; 4-edge unroll.
__global__ void spmm_csr_kernel() {
    int t = blockIdx.x * blockDim.x + threadIdx.x;
    int r = t >> 3;                 // row id
    if (r >= N_NODES_) return;
    int l = t & 7;                  // lane-slice: columns [l*8, l*8+8)
    int beg = __ldg(&g_row_off[r]);
    int end = __ldg(&g_row_off[r + 1]);
    float a0 = 0.f, a1 = 0.f, a2 = 0.f, a3 = 0.f;
    float a4 = 0.f, a5 = 0.f, a6 = 0.f, a7 = 0.f;
    int e = beg;
    for (; e + 4 <= end; e += 4) {
        int2 E0 = __ldg(&g_edge_s[e + 0]);
        int2 E1 = __ldg(&g_edge_s[e + 1]);
        int2 E2 = __ldg(&g_edge_s[e + 2]);
        int2 E3 = __ldg(&g_edge_s[e + 3]);
        uint4 w0 = __ldg((const uint4*)g_ego_h + E0.x * 8 + l);
        uint4 w1 = __ldg((const uint4*)g_ego_h + E1.x * 8 + l);
        uint4 w2 = __ldg((const uint4*)g_ego_h + E2.x * 8 + l);
        uint4 w3 = __ldg((const uint4*)g_ego_h + E3.x * 8 + l);
        float v0 = __int_as_float(E0.y);
        float v1 = __int_as_float(E1.y);
        float v2 = __int_as_float(E2.y);
        float v3 = __int_as_float(E3.y);
#define ACC_EDGE(W, V)                                              \
        {                                                           \
            float2 p0 = __half22float2(*(const __half2*)&W.x);     \
            float2 p1 = __half22float2(*(const __half2*)&W.y);     \
            float2 p2 = __half22float2(*(const __half2*)&W.z);     \
            float2 p3 = __half22float2(*(const __half2*)&W.w);     \
            a0 += p0.x * V; a1 += p0.y * V;                         \
            a2 += p1.x * V; a3 += p1.y * V;                         \
            a4 += p2.x * V; a5 += p2.y * V;                         \
            a6 += p3.x * V; a7 += p3.y * V;                         \
        }
        ACC_EDGE(w0, v0)
        ACC_EDGE(w1, v1)
        ACC_EDGE(w2, v2)
        ACC_EDGE(w3, v3)
    }
    for (; e < end; e++) {
        int2 E = __ldg(&g_edge_s[e]);
        uint4 w = __ldg((const uint4*)g_ego_h + E.x * 8 + l);
        float v = __int_as_float(E.y);
        ACC_EDGE(w, v)
    }
#undef ACC_EDGE
    __half2 h0 = __floats2half2_rn(a0, a1);
    __half2 h1 = __floats2half2_rn(a2, a3);
    __half2 h2 = __floats2half2_rn(a4, a5);
    __half2 h3 = __floats2half2_rn(a6, a7);
    uint4 pk;
    pk.x = *(unsigned*)&h0; pk.y = *(unsigned*)&h1;
    pk.z = *(unsigned*)&h2; pk.w = *(unsigned*)&h3;
    ((uint4*)g_side_h)[r * 8 + l] = pk;        // one STG.128 per lane
}

// ---------------- tensor-core transform + leaky_relu + L2-normalize ----------
__global__ void transform_kernel(const float* __restrict__ Wgc,
                                 const float* __restrict__ bgc,
                                 const float* __restrict__ Wbi,
                                 const float* __restrict__ bbi,
                                 int layer) {
    extern __shared__ char sh[];
    __half* A_h = (__half*)(sh + SH_A);   // [64][A_LD]
    __half* B_h = (__half*)(sh + SH_B);   // [128][B_LD]
    float*  C_f = (float*) (sh + SH_C);   // [64][C_LD]
    float*  bs  = (float*) (sh + SH_BS);  // [64]

    const int tid = threadIdx.x;
    const int rowBase = blockIdx.x * 64;

    // stage B = [Wg; Wb] as fp16 (coalesced float4 loads)
    for (int i = tid; i < 1024; i += 256) {
        int k  = i >> 4;
        int n4 = i & 15;
        float4 wg = __ldg((const float4*)Wgc + i);
        float4 wb = __ldg((const float4*)Wbi + i);
        __half2* dg = (__half2*)&B_h[k * B_LD + n4 * 4];
        dg[0] = __floats2half2_rn(wg.x, wg.y);
        dg[1] = __floats2half2_rn(wg.z, wg.w);
        __half2* db = (__half2*)&B_h[(64 + k) * B_LD + n4 * 4];
        db[0] = __floats2half2_rn(wb.x, wb.y);
        db[1] = __floats2half2_rn(wb.z, wb.w);
    }
    if (tid < 64) bs[tid] = __ldg(bgc + tid) + __ldg(bbi + tid);

    // stage A = [S | ego*S] straight from fp16 state (coalesced uint2 loads)
    for (int i = tid; i < 1024; i += 256) {
        int r  = i >> 4;
        int c4 = i & 15;
        int gr = rowBase + r;
        uint2 sb = make_uint2(0u, 0u);
        uint2 eb = make_uint2(0u, 0u);
        if (gr < N_NODES_) {
            sb = ((const uint2*)g_side_h)[gr * 16 + c4];
            eb = ((const uint2*)g_ego_h )[gr * 16 + c4];
        }
        __half2 s0 = *(const __half2*)&sb.x;
        __half2 s1 = *(const __half2*)&sb.y;
        __half2 e0 = *(const __half2*)&eb.x;
        __half2 e1 = *(const __half2*)&eb.y;
        __half2* ds = (__half2*)&A_h[r * A_LD + c4 * 4];
        ds[0] = s0;
        ds[1] = s1;
        __half2* dp = (__half2*)&A_h[r * A_LD + 64 + c4 * 4];
        dp[0] = __hmul2(e0, s0);
        dp[1] = __hmul2(e1, s1);
    }
    __syncthreads();

    // wmma: 8 warps, each owns one 16-row tile slice x 2 col tiles
    {
        int w = tid >> 5;
        int rt = w >> 1;
        int ct = (w & 1) * 2;
        wmma::fragment<wmma::accumulator, 16, 16, 16, float> c0, c1;
        wmma::fill_fragment(c0, 0.0f);
        wmma::fill_fragment(c1, 0.0f);
#pragma unroll
        for (int k = 0; k < 8; k++) {
            wmma::fragment<wmma::matrix_a, 16, 16, 16, __half, wmma::row_major> a;
            wmma::fragment<wmma::matrix_b, 16, 16, 16, __half, wmma::row_major> b0, b1;
            wmma::load_matrix_sync(a, &A_h[rt * 16 * A_LD + k * 16], A_LD);
            wmma::load_matrix_sync(b0, &B_h[k * 16 * B_LD + ct * 16], B_LD);
            wmma::load_matrix_sync(b1, &B_h[k * 16 * B_LD + (ct + 1) * 16], B_LD);
            wmma::mma_sync(c0, a, b0, c0);
            wmma::mma_sync(c1, a, b1, c1);
        }
        wmma::store_matrix_sync(&C_f[rt * 16 * C_LD + ct * 16], c0, C_LD, wmma::mem_row_major);
        wmma::store_matrix_sync(&C_f[rt * 16 * C_LD + (ct + 1) * 16], c1, C_LD, wmma::mem_row_major);
    }
    __syncthreads();

    // epilogue: bias + leaky, row-norm across 16 tx lanes, fp16 writes
    const int tx = tid & 15;
    const int ty = tid >> 4;
    const int colBase = tx * 4;
    float b0 = bs[colBase + 0], b1 = bs[colBase + 1];
    float b2 = bs[colBase + 2], b3 = bs[colBase + 3];
#pragma unroll
    for (int i = 0; i < 4; i++) {
        int r = ty * 4 + i;
        float4 xc = *(const float4*)&C_f[r * C_LD + colBase];
        float x0 = xc.x + b0;
        float x1 = xc.y + b1;
        float x2 = xc.z + b2;
        float x3 = xc.w + b3;
        x0 = fmaxf(x0, NEG_SLOPE * x0);
        x1 = fmaxf(x1, NEG_SLOPE * x1);
        x2 = fmaxf(x2, NEG_SLOPE * x2);
        x3 = fmaxf(x3, NEG_SLOPE * x3);
        float sq = x0 * x0 + x1 * x1 + x2 * x2 + x3 * x3;
#pragma unroll
        for (int off = 1; off < 16; off <<= 1)
            sq += __shfl_xor_sync(0xffffffffu, sq, off);
        int gr = rowBase + r;
        if (gr < N_NODES_) {
            float inv = 1.0f / fmaxf(sqrtf(sq), EPS_);
            __half2 n0 = __floats2half2_rn(x0 * inv, x1 * inv);
            __half2 n1 = __floats2half2_rn(x2 * inv, x3 * inv);
            uint2 npk;
            npk.x = *(unsigned*)&n0;
            npk.y = *(unsigned*)&n1;
            *(uint2*)&g_all_h[(size_t)gr * 256 + (layer + 1) * 64 + colBase] = npk;
            if (layer < N_LAYERS - 1) {
                __half2 h0 = __floats2half2_rn(x0, x1);
                __half2 h1 = __floats2half2_rn(x2, x3);
                uint2 pk;
                pk.x = *(unsigned*)&h0;
                pk.y = *(unsigned*)&h1;
                *(uint2*)&g_ego_h[(size_t)gr * EMB + colBase] = pk;
            }
        }
    }
}

// ---------------- GMF head: sigmoid((u*i)@W_out + b_out), fp16 embeddings ----
__global__ void head_kernel(const int* __restrict__ uidx,
                            const int* __restrict__ iidx,
                            const float* __restrict__ Wout,
                            const float* __restrict__ bout,
                            float* __restrict__ out) {
    int gw = (blockIdx.x * blockDim.x + threadIdx.x) >> 5;
    if (gw >= BATCH_) return;
    int lane = threadIdx.x & 31;
    int u  = __ldg(&uidx[gw]);
    int it = __ldg(&iidx[gw]) + N_USER;
    // row = 256 halves = 32 uint4; one uint4 (8 halves) per lane
    uint4 ua = *((const uint4*)(g_all_h + (size_t)u  * 256) + lane);
    uint4 ia = *((const uint4*)(g_all_h + (size_t)it * 256) + lane);
    float4 w0 = __ldg((const float4*)Wout + lane * 2);
    float4 w1 = __ldg((const float4*)Wout + lane * 2 + 1);
    float2 u0 = __half22float2(*(const __half2*)&ua.x);
    float2 u1 = __half22float2(*(const __half2*)&ua.y);
    float2 u2 = __half22float2(*(const __half2*)&ua.z);
    float2 u3 = __half22float2(*(const __half2*)&ua.w);
    float2 i0 = __half22float2(*(const __half2*)&ia.x);
    float2 i1 = __half22float2(*(const __half2*)&ia.y);
    float2 i2 = __half22float2(*(const __half2*)&ia.z);
    float2 i3 = __half22float2(*(const __half2*)&ia.w);
    float acc = u0.x * i0.x * w0.x + u0.y * i0.y * w0.y
              + u1.x * i1.x * w0.z + u1.y * i1.y * w0.w
              + u2.x * i2.x * w1.x + u2.y * i2.y * w1.y
              + u3.x * i3.x * w1.z + u3.y * i3.y * w1.w;
#pragma unroll
    for (int off = 16; off; off >>= 1)
        acc += __shfl_xor_sync(0xffffffffu, acc, off);
    if (lane == 0) {
        float z = acc + __ldg(bout);
        out[gw] = 1.0f / (1.0f + expf(-z));
    }
}

// ---------------- launch ------------------------------------------------------
extern "C" void kernel_launch(void* const* d_in, const int* in_sizes, int n_in,
                              void* d_out, int out_size) {
    const int*   user_idx = (const int*)  d_in[0];
    const int*   item_idx = (const int*)  d_in[1];
    const int*   adj_rows = (const int*)  d_in[2];
    const int*   adj_cols = (const int*)  d_in[3];
    const int*   adj_vals = (const int*)  d_in[4];   // raw bits for scatter
    const float* user_emb = (const float*)d_in[5];
    const float* item_emb = (const float*)d_in[6];
    const float* W_gc     = (const float*)d_in[7];
    const float* b_gc     = (const float*)d_in[8];
    const float* W_bi     = (const float*)d_in[9];
    const float* b_bi     = (const float*)d_in[10];
    const float* W_out    = (const float*)d_in[11];
    const float* b_out    = (const float*)d_in[12];
    float* out = (float*)d_out;

    cudaFuncSetAttribute(transform_kernel,
                         cudaFuncAttributeMaxDynamicSharedMemorySize, SH_TOT);

    const int vec_blocks = (N_NODES_ * EMB / 4) / 256;   // 9375 (covers NNZ/4 too)
    init_kernel<<<vec_blocks, 256>>>(user_emb, item_emb, adj_rows);

    scan_kernel<<<1, 1024>>>();
    scatter_kernel<<<(NNZ_ / 16 + 255) / 256, 256>>>(adj_rows, adj_cols, adj_vals);

    const int spmm_blocks = (N_NODES_ * 8 + 255) / 256;  // 4688
    const int tile_blocks = (N_NODES_ + 63) / 64;        // 2344

    for (int l = 0; l < N_LAYERS; l++) {
        spmm_csr_kernel<<<spmm_blocks, 256>>>();
        transform_kernel<<<tile_blocks, 256, SH_TOT>>>(W_gc + l * EMB * EMB,
                                                       b_gc + l * EMB,
                                                       W_bi + l * EMB * EMB,
                                                       b_bi + l * EMB,
                                                       l);
    }

    head_kernel<<<(BATCH_ * 32) / 256, 256>>>(user_idx, item_idx, W_out, b_out, out);
}

// round 17
// speedup vs baseline: 1.0320x; 1.0320x over previous
#include <cuda_runtime.h>
#include <cuda_fp16.h>
#include <mma.h>
#include <math.h>

using namespace nvcuda;

#define N_USER   100000
#define N_ITEM   50000
#define N_NODES_ (N_USER + N_ITEM)   // 150000
#define NNZ_     4800000
#define EMB      64
#define N_LAYERS 3
#define BATCH_   16384
#define EPS_     1e-12f
#define NEG_SLOPE 0.2f

// shared-memory layout for 128-row transform (bytes)
#define A_LD   136                    // halves per row of A=[S|P]
#define B_LD   72                     // halves per row of B=[Wg;Wb]
#define C_LD   72                     // floats per row of C
#define SH_A   0
#define SH_B   (128 * A_LD * 2)                   // 34816
#define SH_BS  (SH_B + 128 * B_LD * 2)            // 53248
#define SH_TOT (SH_BS + 64 * 4)                   // 53504
#define SH_C   0                                  // C aliases A/B (post-MMA only)

// ---------------- scratch (device globals: allocation-free rule) -------------
__device__ __half g_ego_h [N_NODES_ * EMB];     // fp16 ego
__device__ __half g_side_h[N_NODES_ * EMB];     // fp16 A_hat @ ego
__device__ __half g_all_h [N_NODES_ * 4 * EMB]; // fp16 concat of 4 blocks
__device__ __half g_Wh    [N_LAYERS * 128 * EMB]; // fp16 [Wg;Wb] per layer
// CSR build scratch.  g_row_cnt is zero-initialized at module load and
// re-zeroed by scan_kernel after it is consumed -> every replay sees zeros.
__device__ int   g_row_cnt[N_NODES_];
__device__ int   g_row_cur[N_NODES_];           // seeded with row offsets by scan
__device__ int   g_row_off[N_NODES_ + 1];
__device__ int2  g_edge_s [NNZ_];               // packed (col, val_bits), row-sorted

// ------- init: ego_h = fp16(concat(ue, ie)); g_all[:,0:64]; count; weights ---
__global__ void init_kernel(const float* __restrict__ ue, const float* __restrict__ ie,
                            const int* __restrict__ rows,
                            const float* __restrict__ Wgc, const float* __restrict__ Wbi) {
    int idx = blockIdx.x * blockDim.x + threadIdx.x;      // half4 (uint2) index
    const int total = N_NODES_ * EMB / 4;                 // 2.4M
    if (idx < total) {
        int node = idx >> 4;
        int c4   = idx & 15;
        float4 v;
        if (node < N_USER) v = __ldg((const float4*)ue + node * 16 + c4);
        else               v = __ldg((const float4*)ie + (node - N_USER) * 16 + c4);
        __half2 h0 = __floats2half2_rn(v.x, v.y);
        __half2 h1 = __floats2half2_rn(v.z, v.w);
        uint2 pk;
        pk.x = *(unsigned*)&h0;
        pk.y = *(unsigned*)&h1;
        ((uint2*)g_ego_h)[idx] = pk;
        ((uint2*)g_all_h)[node * 64 + c4] = pk;   // row = 256 halves = 64 uint2
    }
    if (idx < NNZ_ / 4) {             // fused degree count (cnt pre-zeroed)
        int4 r4 = __ldg((const int4*)rows + idx);
        atomicAdd(&g_row_cnt[r4.x], 1);
        atomicAdd(&g_row_cnt[r4.y], 1);
        atomicAdd(&g_row_cnt[r4.z], 1);
        atomicAdd(&g_row_cnt[r4.w], 1);
    }
    // fused weight conversion: 3 layers x 4096 float4-groups? use float4 per thread
    // 3*4096 floats per matrix pair handled as float4: 3*1024 groups per matrix.
    if (idx < N_LAYERS * 1024) {
        int l = idx / 1024;
        int g = idx - l * 1024;       // float4 group within 64x64 matrix
        int k = g >> 4;               // row 0..63
        int n4 = g & 15;
        float4 wg = __ldg((const float4*)(Wgc + l * EMB * EMB) + g);
        float4 wb = __ldg((const float4*)(Wbi + l * EMB * EMB) + g);
        __half2 g0 = __floats2half2_rn(wg.x, wg.y);
        __half2 g1 = __floats2half2_rn(wg.z, wg.w);
        __half2 b0 = __floats2half2_rn(wb.x, wb.y);
        __half2 b1 = __floats2half2_rn(wb.z, wb.w);
        uint2 pg, pb;
        pg.x = *(unsigned*)&g0; pg.y = *(unsigned*)&g1;
        pb.x = *(unsigned*)&b0; pb.y = *(unsigned*)&b1;
        __half* base = g_Wh + (size_t)l * 128 * EMB;
        *(uint2*)&base[k * EMB + n4 * 4]        = pg;   // Wg rows 0..63
        *(uint2*)&base[(64 + k) * EMB + n4 * 4] = pb;   // Wb rows 64..127
    }
}

// ---------------- CSR build: coalesced wave-scan (single block, 1024 thr) ----
__global__ void scan_kernel() {
    __shared__ int warp_sums[32];
    const int NWAVES = (N_NODES_ + 1023) / 1024;   // 147
    int t    = threadIdx.x;
    int lane = t & 31;
    int wid  = t >> 5;
    int carry = 0;
    for (int w = 0; w < NWAVES; w++) {
        int idx = w * 1024 + t;
        int c = 0;
        if (idx < N_NODES_) {
            c = g_row_cnt[idx];
            g_row_cnt[idx] = 0;     // reset for next replay
        }
        int x = c;                  // inclusive warp scan
#pragma unroll
        for (int off = 1; off < 32; off <<= 1) {
            int y = __shfl_up_sync(0xffffffffu, x, off);
            if (lane >= off) x += y;
        }
        if (lane == 31) warp_sums[wid] = x;
        __syncthreads();
        if (wid == 0) {
            int wv = warp_sums[lane];
#pragma unroll
            for (int off = 1; off < 32; off <<= 1) {
                int y = __shfl_up_sync(0xffffffffu, wv, off);
                if (lane >= off) wv += y;
            }
            warp_sums[lane] = wv;
        }
        __syncthreads();
        int warp_excl = (wid > 0) ? warp_sums[wid - 1] : 0;
        int excl = carry + warp_excl + (x - c);
        if (idx < N_NODES_) {
            g_row_off[idx] = excl;
            g_row_cur[idx] = excl;  // cursor starts at row start
        }
        carry += warp_sums[31];
        __syncthreads();
    }
    if (t == 0) g_row_off[N_NODES_] = carry;   // total = NNZ
}

// ---------------- CSR build: scatter edges (8 chains/thread) ------------------
__global__ void scatter_kernel(const int* __restrict__ rows,
                               const int* __restrict__ cols,
                               const int* __restrict__ vals) {
    int q = blockIdx.x * blockDim.x + threadIdx.x;   // octet id
    if (q >= NNZ_ / 8) return;
    int4 ra = __ldg((const int4*)rows + q * 2);
    int4 rb = __ldg((const int4*)rows + q * 2 + 1);
    int4 ca = __ldg((const int4*)cols + q * 2);
    int4 cb = __ldg((const int4*)cols + q * 2 + 1);
    int4 va = __ldg((const int4*)vals + q * 2);      // val bits
    int4 vb = __ldg((const int4*)vals + q * 2 + 1);
    int r[8] = {ra.x, ra.y, ra.z, ra.w, rb.x, rb.y, rb.z, rb.w};
    int c[8] = {ca.x, ca.y, ca.z, ca.w, cb.x, cb.y, cb.z, cb.w};
    int v[8] = {va.x, va.y, va.z, va.w, vb.x, vb.y, vb.z, vb.w};
    int p[8];
#pragma unroll
    for (int u = 0; u < 8; u++) p[u] = atomicAdd(&g_row_cur[r[u]], 1);
#pragma unroll
    for (int u = 0; u < 8; u++) g_edge_s[p[u]] = make_int2(c[u], v[u]);
}

// ---------------- CSR SpMM: fp16 gather (16B/lane), fp32 accum, fp16 store ----
// 8 lanes per row; each lane owns 8 consecutive columns; 4-edge unroll.
__global__ void spmm_csr_kernel() {
    int t = blockIdx.x * blockDim.x + threadIdx.x;
    int r = t >> 3;                 // row id
    if (r >= N_NODES_) return;
    int l = t & 7;                  // lane-slice: columns [l*8, l*8+8)
    int beg = __ldg(&g_row_off[r]);
    int end = __ldg(&g_row_off[r + 1]);
    float a0 = 0.f, a1 = 0.f, a2 = 0.f, a3 = 0.f;
    float a4 = 0.f, a5 = 0.f, a6 = 0.f, a7 = 0.f;
    int e = beg;
    for (; e + 4 <= end; e += 4) {
        int2 E0 = __ldg(&g_edge_s[e + 0]);
        int2 E1 = __ldg(&g_edge_s[e + 1]);
        int2 E2 = __ldg(&g_edge_s[e + 2]);
        int2 E3 = __ldg(&g_edge_s[e + 3]);
        uint4 w0 = __ldg((const uint4*)g_ego_h + E0.x * 8 + l);
        uint4 w1 = __ldg((const uint4*)g_ego_h + E1.x * 8 + l);
        uint4 w2 = __ldg((const uint4*)g_ego_h + E2.x * 8 + l);
        uint4 w3 = __ldg((const uint4*)g_ego_h + E3.x * 8 + l);
        float v0 = __int_as_float(E0.y);
        float v1 = __int_as_float(E1.y);
        float v2 = __int_as_float(E2.y);
        float v3 = __int_as_float(E3.y);
#define ACC_EDGE(W, V)                                              \
        {                                                           \
            float2 p0 = __half22float2(*(const __half2*)&W.x);     \
            float2 p1 = __half22float2(*(const __half2*)&W.y);     \
            float2 p2 = __half22float2(*(const __half2*)&W.z);     \
            float2 p3 = __half22float2(*(const __half2*)&W.w);     \
            a0 += p0.x * V; a1 += p0.y * V;                         \
            a2 += p1.x * V; a3 += p1.y * V;                         \
            a4 += p2.x * V; a5 += p2.y * V;                         \
            a6 += p3.x * V; a7 += p3.y * V;                         \
        }
        ACC_EDGE(w0, v0)
        ACC_EDGE(w1, v1)
        ACC_EDGE(w2, v2)
        ACC_EDGE(w3, v3)
    }
    for (; e < end; e++) {
        int2 E = __ldg(&g_edge_s[e]);
        uint4 w = __ldg((const uint4*)g_ego_h + E.x * 8 + l);
        float v = __int_as_float(E.y);
        ACC_EDGE(w, v)
    }
#undef ACC_EDGE
    __half2 h0 = __floats2half2_rn(a0, a1);
    __half2 h1 = __floats2half2_rn(a2, a3);
    __half2 h2 = __floats2half2_rn(a4, a5);
    __half2 h3 = __floats2half2_rn(a6, a7);
    uint4 pk;
    pk.x = *(unsigned*)&h0; pk.y = *(unsigned*)&h1;
    pk.z = *(unsigned*)&h2; pk.w = *(unsigned*)&h3;
    ((uint4*)g_side_h)[r * 8 + l] = pk;        // one STG.128 per lane
}

// ------- tensor-core transform, 128-row tiles, 512 threads, fp16 weights -----
__global__ void transform_kernel(const float* __restrict__ bgc,
                                 const float* __restrict__ bbi,
                                 int layer) {
    extern __shared__ char sh[];
    __half* A_h = (__half*)(sh + SH_A);   // [128][A_LD]
    __half* B_h = (__half*)(sh + SH_B);   // [128][B_LD]
    float*  C_f = (float*) (sh + SH_C);   // [128][C_LD] (aliases A/B post-MMA)
    float*  bs  = (float*) (sh + SH_BS);  // [64]

    const int tid = threadIdx.x;          // 0..511
    const int rowBase = blockIdx.x * 128;
    const __half* Wl = g_Wh + (size_t)layer * 128 * EMB;

    // stage B = fp16 [Wg;Wb] (128 rows x 16 uint2 = 2048 groups, 4 iters)
    for (int i = tid; i < 2048; i += 512) {
        int k  = i >> 4;
        int n4 = i & 15;
        uint2 w = *(const uint2*)&Wl[k * EMB + n4 * 4];
        *(uint2*)&B_h[k * B_LD + n4 * 4] = w;
    }
    if (tid < 64) bs[tid] = __ldg(bgc + layer * EMB + tid) + __ldg(bbi + layer * EMB + tid);

    // stage A = [S | ego*S] from fp16 state (128 rows x 16 uint2, 4 iters)
    for (int i = tid; i < 2048; i += 512) {
        int r  = i >> 4;
        int c4 = i & 15;
        int gr = rowBase + r;
        uint2 sb = make_uint2(0u, 0u);
        uint2 eb = make_uint2(0u, 0u);
        if (gr < N_NODES_) {
            sb = ((const uint2*)g_side_h)[gr * 16 + c4];
            eb = ((const uint2*)g_ego_h )[gr * 16 + c4];
        }
        __half2 s0 = *(const __half2*)&sb.x;
        __half2 s1 = *(const __half2*)&sb.y;
        __half2 e0 = *(const __half2*)&eb.x;
        __half2 e1 = *(const __half2*)&eb.y;
        __half2* ds = (__half2*)&A_h[r * A_LD + c4 * 4];
        ds[0] = s0;
        ds[1] = s1;
        __half2* dp = (__half2*)&A_h[r * A_LD + 64 + c4 * 4];
        dp[0] = __hmul2(e0, s0);
        dp[1] = __hmul2(e1, s1);
    }
    __syncthreads();

    // wmma: 16 warps; warp w -> row tile w>>1 (0..7), col tiles (w&1)*2, +1
    int w  = tid >> 5;
    int rt = w >> 1;
    int ct = (w & 1) * 2;
    wmma::fragment<wmma::accumulator, 16, 16, 16, float> c0, c1;
    wmma::fill_fragment(c0, 0.0f);
    wmma::fill_fragment(c1, 0.0f);
#pragma unroll
    for (int k = 0; k < 8; k++) {
        wmma::fragment<wmma::matrix_a, 16, 16, 16, __half, wmma::row_major> a;
        wmma::fragment<wmma::matrix_b, 16, 16, 16, __half, wmma::row_major> b0, b1;
        wmma::load_matrix_sync(a, &A_h[rt * 16 * A_LD + k * 16], A_LD);
        wmma::load_matrix_sync(b0, &B_h[k * 16 * B_LD + ct * 16], B_LD);
        wmma::load_matrix_sync(b1, &B_h[k * 16 * B_LD + (ct + 1) * 16], B_LD);
        wmma::mma_sync(c0, a, b0, c0);
        wmma::mma_sync(c1, a, b1, c1);
    }
    __syncthreads();                 // all MMA reads of A/B complete (C aliases)
    wmma::store_matrix_sync(&C_f[rt * 16 * C_LD + ct * 16], c0, C_LD, wmma::mem_row_major);
    wmma::store_matrix_sync(&C_f[rt * 16 * C_LD + (ct + 1) * 16], c1, C_LD, wmma::mem_row_major);
    __syncthreads();

    // epilogue: bias + leaky, row-norm across 16 tx lanes, fp16 writes
    const int tx = tid & 15;
    const int ty = tid >> 4;          // 0..31
    const int colBase = tx * 4;
    float b0 = bs[colBase + 0], b1 = bs[colBase + 1];
    float b2 = bs[colBase + 2], b3 = bs[colBase + 3];
#pragma unroll
    for (int i = 0; i < 4; i++) {
        int r = ty * 4 + i;           // 0..127
        float4 xc = *(const float4*)&C_f[r * C_LD + colBase];
        float x0 = xc.x + b0;
        float x1 = xc.y + b1;
        float x2 = xc.z + b2;
        float x3 = xc.w + b3;
        x0 = fmaxf(x0, NEG_SLOPE * x0);
        x1 = fmaxf(x1, NEG_SLOPE * x1);
        x2 = fmaxf(x2, NEG_SLOPE * x2);
        x3 = fmaxf(x3, NEG_SLOPE * x3);
        float sq = x0 * x0 + x1 * x1 + x2 * x2 + x3 * x3;
#pragma unroll
        for (int off = 1; off < 16; off <<= 1)
            sq += __shfl_xor_sync(0xffffffffu, sq, off);
        int gr = rowBase + r;
        if (gr < N_NODES_) {
            float inv = 1.0f / fmaxf(sqrtf(sq), EPS_);
            __half2 n0 = __floats2half2_rn(x0 * inv, x1 * inv);
            __half2 n1 = __floats2half2_rn(x2 * inv, x3 * inv);
            uint2 npk;
            npk.x = *(unsigned*)&n0;
            npk.y = *(unsigned*)&n1;
            *(uint2*)&g_all_h[(size_t)gr * 256 + (layer + 1) * 64 + colBase] = npk;
            if (layer < N_LAYERS - 1) {
                __half2 h0 = __floats2half2_rn(x0, x1);
                __half2 h1 = __floats2half2_rn(x2, x3);
                uint2 pk;
                pk.x = *(unsigned*)&h0;
                pk.y = *(unsigned*)&h1;
                *(uint2*)&g_ego_h[(size_t)gr * EMB + colBase] = pk;
            }
        }
    }
}

// ---------------- GMF head: sigmoid((u*i)@W_out + b_out), fp16 embeddings ----
__global__ void head_kernel(const int* __restrict__ uidx,
                            const int* __restrict__ iidx,
                            const float* __restrict__ Wout,
                            const float* __restrict__ bout,
                            float* __restrict__ out) {
    int gw = (blockIdx.x * blockDim.x + threadIdx.x) >> 5;
    if (gw >= BATCH_) return;
    int lane = threadIdx.x & 31;
    int u  = __ldg(&uidx[gw]);
    int it = __ldg(&iidx[gw]) + N_USER;
    uint4 ua = *((const uint4*)(g_all_h + (size_t)u  * 256) + lane);
    uint4 ia = *((const uint4*)(g_all_h + (size_t)it * 256) + lane);
    float4 w0 = __ldg((const float4*)Wout + lane * 2);
    float4 w1 = __ldg((const float4*)Wout + lane * 2 + 1);
    float2 u0 = __half22float2(*(const __half2*)&ua.x);
    float2 u1 = __half22float2(*(const __half2*)&ua.y);
    float2 u2 = __half22float2(*(const __half2*)&ua.z);
    float2 u3 = __half22float2(*(const __half2*)&ua.w);
    float2 i0 = __half22float2(*(const __half2*)&ia.x);
    float2 i1 = __half22float2(*(const __half2*)&ia.y);
    float2 i2 = __half22float2(*(const __half2*)&ia.z);
    float2 i3 = __half22float2(*(const __half2*)&ia.w);
    float acc = u0.x * i0.x * w0.x + u0.y * i0.y * w0.y
              + u1.x * i1.x * w0.z + u1.y * i1.y * w0.w
              + u2.x * i2.x * w1.x + u2.y * i2.y * w1.y
              + u3.x * i3.x * w1.z + u3.y * i3.y * w1.w;
#pragma unroll
    for (int off = 16; off; off >>= 1)
        acc += __shfl_xor_sync(0xffffffffu, acc, off);
    if (lane == 0) {
        float z = acc + __ldg(bout);
        out[gw] = 1.0f / (1.0f + expf(-z));
    }
}

// ---------------- launch ------------------------------------------------------
extern "C" void kernel_launch(void* const* d_in, const int* in_sizes, int n_in,
                              void* d_out, int out_size) {
    const int*   user_idx = (const int*)  d_in[0];
    const int*   item_idx = (const int*)  d_in[1];
    const int*   adj_rows = (const int*)  d_in[2];
    const int*   adj_cols = (const int*)  d_in[3];
    const int*   adj_vals = (const int*)  d_in[4];   // raw bits for scatter
    const float* user_emb = (const float*)d_in[5];
    const float* item_emb = (const float*)d_in[6];
    const float* W_gc     = (const float*)d_in[7];
    const float* b_gc     = (const float*)d_in[8];
    const float* W_bi     = (const float*)d_in[9];
    const float* b_bi     = (const float*)d_in[10];
    const float* W_out    = (const float*)d_in[11];
    const float* b_out    = (const float*)d_in[12];
    float* out = (float*)d_out;

    cudaFuncSetAttribute(transform_kernel,
                         cudaFuncAttributeMaxDynamicSharedMemorySize, SH_TOT);

    const int vec_blocks = (N_NODES_ * EMB / 4) / 256;   // 9375 (covers NNZ/4, weights)
    init_kernel<<<vec_blocks, 256>>>(user_emb, item_emb, adj_rows, W_gc, W_bi);

    scan_kernel<<<1, 1024>>>();
    scatter_kernel<<<(NNZ_ / 8 + 255) / 256, 256>>>(adj_rows, adj_cols, adj_vals);

    const int spmm_blocks = (N_NODES_ * 8 + 255) / 256;  // 4688
    const int tile_blocks = (N_NODES_ + 127) / 128;      // 1172

    for (int l = 0; l < N_LAYERS; l++) {
        spmm_csr_kernel<<<spmm_blocks, 256>>>();
        transform_kernel<<<tile_blocks, 512, SH_TOT>>>(b_gc, b_bi, l);
    }

    head_kernel<<<(BATCH_ * 32) / 256, 256>>>(user_idx, item_idx, W_out, b_out, out);
}